// round 14
// baseline (speedup 1.0000x reference)
#include <cuda_runtime.h>
#include <math.h>
#include <stdint.h>

#define BATCH 8
#define SEQ   2048
#define CDIM  1024
#define HS    64
#define M_TOTAL (BATCH * SEQ)   // 16384

#define QROWS  128              // Q rows per attention CTA
#define NQT2   (SEQ / QROWS)    // 16 query tiles per batch
#define NCHUNK 8                // 8 KV chunks of 256 keys (4 tiles of 64)

// Scratch (device globals: allowed).
__device__ float g_q[M_TOTAL * HS];
__device__ float g_k[M_TOTAL * HS];
__device__ float g_v[M_TOTAL * HS];
__device__ float g_po[(size_t)BATCH * NQT2 * NCHUNK * QROWS * 64];
__device__ float g_pm[BATCH * NQT2 * NCHUNK * QROWS];
__device__ float g_pl[BATCH * NQT2 * NCHUNK * QROWS];
// Pre-split weights (tf32 hi/lo), layout [which][k][n]
__device__ float g_wh[3 * CDIM * HS];
__device__ float g_wl[3 * CDIM * HS];

// ---------------------------------------------------------------------------
// helpers
// ---------------------------------------------------------------------------
__device__ __forceinline__ float tf32r(float x) {
    uint32_t u;
    asm("cvt.rna.tf32.f32 %0, %1;" : "=r"(u) : "f"(x));
    return __uint_as_float(u);
}

__device__ __forceinline__ void mma_tf32(float4& d, const float* a, const float* b) {
    asm volatile(
        "mma.sync.aligned.m16n8k8.row.col.f32.tf32.tf32.f32 "
        "{%0,%1,%2,%3}, {%4,%5,%6,%7}, {%8,%9}, {%0,%1,%2,%3};"
        : "+f"(d.x), "+f"(d.y), "+f"(d.z), "+f"(d.w)
        : "r"(__float_as_uint(a[0])), "r"(__float_as_uint(a[1])),
          "r"(__float_as_uint(a[2])), "r"(__float_as_uint(a[3])),
          "r"(__float_as_uint(b[0])), "r"(__float_as_uint(b[1])));
}

__device__ __forceinline__ void cpa16(void* smem_dst, const void* gmem_src) {
    uint32_t s = (uint32_t)__cvta_generic_to_shared(smem_dst);
    asm volatile("cp.async.cg.shared.global [%0], [%1], 16;" :: "r"(s), "l"(gmem_src));
}
#define CP_COMMIT() asm volatile("cp.async.commit_group;")
#define CP_WAIT(n)  asm volatile("cp.async.wait_group %0;" :: "n"(n))

// ---------------------------------------------------------------------------
// Kernel 0: split W into tf32 hi/lo. 3*1024*64 = 196608 floats = 49152 float4.
// ---------------------------------------------------------------------------
__global__ __launch_bounds__(256) void wsplit(
    const float* __restrict__ Wq, const float* __restrict__ Wk,
    const float* __restrict__ Wv)
{
    const int idx = blockIdx.x * 256 + threadIdx.x;      // float4 id, 0..49151
    const float* W = (idx < 16384) ? Wq : (idx < 32768 ? Wk : Wv);
    const int local = (idx & 16383) * 4;
    float4 w = *(const float4*)&W[local];
    float4 h, l;
    h.x = tf32r(w.x); l.x = tf32r(w.x - h.x);
    h.y = tf32r(w.y); l.y = tf32r(w.y - h.y);
    h.z = tf32r(w.z); l.z = tf32r(w.z - h.z);
    h.w = tf32r(w.w); l.w = tf32r(w.w - h.w);
    *(float4*)&g_wh[idx * 4] = h;
    *(float4*)&g_wl[idx * 4] = l;
}

// ---------------------------------------------------------------------------
// Kernel 1: QKV projection, 2-term TF32 mma (X truncated, W exact via hi+lo).
// ---------------------------------------------------------------------------
#define QBM 128
#define QBK 16
#define A_STR 20
#define B_STR 72
#define NKITER (CDIM / QBK)   // 64

__global__ __launch_bounds__(256) void qkv_tc(
    const float* __restrict__ xq, const float* __restrict__ xkv)
{
    const int which = blockIdx.y;                 // 0=Q, 1=K, 2=V
    const float* __restrict__ X  = (which == 0) ? xq : xkv;
    const float* __restrict__ WH = g_wh + which * CDIM * HS;
    const float* __restrict__ WL = g_wl + which * CDIM * HS;
    float* __restrict__ O = (which == 0) ? g_q : (which == 1 ? g_k : g_v);

    __shared__ __align__(16) float As[2][QBM][A_STR];
    __shared__ __align__(16) float Bh[2][QBK][B_STR];
    __shared__ __align__(16) float Bl[2][QBK][B_STR];

    const int tid  = threadIdx.x;
    const int warp = tid >> 5;
    const int lane = tid & 31;
    const int m0   = blockIdx.x * QBM;

    float4 acc[8];
#pragma unroll
    for (int nt = 0; nt < 8; nt++) acc[nt] = make_float4(0.f, 0.f, 0.f, 0.f);

    auto load_tile = [&](int it, int buf) {
        const int k0 = it * QBK;
#pragma unroll
        for (int i = 0; i < 2; i++) {
            int idx = tid + i * 256;       // 0..511
            int r   = idx >> 2;
            int c4  = (idx & 3) * 4;
            cpa16(&As[buf][r][c4], &X[(size_t)(m0 + r) * CDIM + k0 + c4]);
        }
        {
            int r  = tid >> 4;             // 0..15
            int c4 = (tid & 15) * 4;
            cpa16(&Bh[buf][r][c4], &WH[(size_t)(k0 + r) * HS + c4]);
            cpa16(&Bl[buf][r][c4], &WL[(size_t)(k0 + r) * HS + c4]);
        }
    };

    load_tile(0, 0);
    CP_COMMIT();

    const int arow = warp * 16 + (lane >> 2);
    const int kq   = lane & 3;
    const int bcol = lane >> 2;

    for (int it = 0; it < NKITER; it++) {
        const int buf = it & 1;
        if (it + 1 < NKITER) {
            load_tile(it + 1, buf ^ 1);
            CP_COMMIT();
            CP_WAIT(1);
        } else {
            CP_WAIT(0);
        }
        __syncthreads();

#pragma unroll
        for (int kk = 0; kk < 2; kk++) {
            const int ks = kk * 8;
            float ah[4];
            ah[0] = tf32r(As[buf][arow][ks + kq]);
            ah[1] = tf32r(As[buf][arow + 8][ks + kq]);
            ah[2] = tf32r(As[buf][arow][ks + kq + 4]);
            ah[3] = tf32r(As[buf][arow + 8][ks + kq + 4]);
#pragma unroll
            for (int nt = 0; nt < 8; nt++) {
                float bh[2], bl[2];
                bh[0] = Bh[buf][ks + kq][nt * 8 + bcol];
                bh[1] = Bh[buf][ks + kq + 4][nt * 8 + bcol];
                bl[0] = Bl[buf][ks + kq][nt * 8 + bcol];
                bl[1] = Bl[buf][ks + kq + 4][nt * 8 + bcol];
                mma_tf32(acc[nt], ah, bh);
                mma_tf32(acc[nt], ah, bl);
            }
        }
        __syncthreads();
    }

    {
        const int row0 = m0 + warp * 16 + (lane >> 2);
#pragma unroll
        for (int nt = 0; nt < 8; nt++) {
            const int col = nt * 8 + 2 * (lane & 3);
            *(float2*)&O[(size_t)row0 * HS + col] =
                make_float2(acc[nt].x, acc[nt].y);
            *(float2*)&O[(size_t)(row0 + 8) * HS + col] =
                make_float2(acc[nt].z, acc[nt].w);
        }
    }
}

// ---------------------------------------------------------------------------
// Kernel 2: split-KV causal flash attention, 128-row Q tiles.
// grid = (NQT2, NCHUNK, BATCH), block = 256 (8 warps, 16 rows each).
// K/V stored NATURALLY (no permutation): float4 STS; S B-fragments read as
// 2 conflict-free scalar LDS. S and PV both single-pass tf32.
// smem: KVh[64][AST] + Ps[128][AST] = 52224 B.
// ---------------------------------------------------------------------------
#define AST 68

__global__ __launch_bounds__(256) void attn_tc(void)
{
    extern __shared__ float sm[];
    float* KVh = sm;                     // [64][AST]   (K, then V per kt)
    float* Ps  = sm + 64 * AST;          // [128][AST]

    const int qt  = blockIdx.x;          // 0..15 (128-row tiles)
    const int cix = blockIdx.y;          // 0..7
    const int bb  = blockIdx.z;
    if (2 * cix > qt) return;            // chunk entirely above diagonal

    const int tid  = threadIdx.x;
    const int warp = tid >> 5;           // 0..7
    const int lane = tid & 31;
    const int r    = lane >> 2;          // 0..7
    const int kq   = lane & 3;           // quad k
    const float scale = 0.03125f;        // 1024^-0.5

    const int irow_lo = warp * 16 + r;   // 0..127
    const int irow_hi = irow_lo + 8;

    // ---- Q fragments hoisted (single tf32)
    float qh[8][4];
    {
        const float* Qg = g_q + ((size_t)bb * SEQ + qt * QROWS + warp * 16) * HS;
#pragma unroll
        for (int ks = 0; ks < 8; ks++) {
            qh[ks][0] = tf32r(Qg[r * HS + 8 * ks + kq]);
            qh[ks][1] = tf32r(Qg[(r + 8) * HS + 8 * ks + kq]);
            qh[ks][2] = tf32r(Qg[r * HS + 8 * ks + kq + 4]);
            qh[ks][3] = tf32r(Qg[(r + 8) * HS + 8 * ks + kq + 4]);
        }
    }

    float4 o[8];
#pragma unroll
    for (int nt = 0; nt < 8; nt++) o[nt] = make_float4(0.f, 0.f, 0.f, 0.f);
    float m_lo = -INFINITY, m_hi = -INFINITY, l_lo = 0.f, l_hi = 0.f;

    const int kt_begin = cix * 4;
    const int kt_last  = 2 * qt + 1;     // last tile touching this Q block
    const int kt_end   = (cix * 4 + 3 < kt_last) ? (cix * 4 + 3) : kt_last;

    for (int kt = kt_begin; kt <= kt_end; kt++) {
        const float* Kg = g_k + ((size_t)bb * SEQ + kt * 64) * HS;
        const float* Vg = g_v + ((size_t)bb * SEQ + kt * 64) * HS;

        __syncthreads();   // prev-iter V reads (PV) done before K overwrite

        // ---- K load (tf32, natural layout): 4 float4 per thread
#pragma unroll
        for (int i = 0; i < 4; i++) {
            int idx = tid + i * 256;     // float4 id 0..1023
            int row = idx >> 4;
            int c4  = (idx & 15) * 4;
            float4 v = *(const float4*)&Kg[row * HS + c4];
            float4 h4;
            h4.x = tf32r(v.x);
            h4.y = tf32r(v.y);
            h4.z = tf32r(v.z);
            h4.w = tf32r(v.w);
            *(float4*)&KVh[row * AST + c4] = h4;
        }
        __syncthreads();

        // ---- S = Q K^T (single pass; B via 2 conflict-free scalar LDS)
        float4 s[8];
#pragma unroll
        for (int nt = 0; nt < 8; nt++) s[nt] = make_float4(0.f, 0.f, 0.f, 0.f);

#pragma unroll
        for (int ks = 0; ks < 8; ks++) {
#pragma unroll
            for (int nt = 0; nt < 8; nt++) {
                const int jrow = nt * 8 + r;
                float b[2];
                b[0] = KVh[jrow * AST + 8 * ks + kq];
                b[1] = KVh[jrow * AST + 8 * ks + kq + 4];
                mma_tf32(s[nt], qh[ks], b);
            }
        }

        // ---- scale + causal mask.
        // global row = qt*128 + irow; global col = kt*64 + c.
        // mask iff c > irow + rowbias, rowbias = qt*128 - kt*64.
        const int rowbias = qt * QROWS - kt * 64;
        const bool diag = (rowbias < 64);
#pragma unroll
        for (int nt = 0; nt < 8; nt++) {
            const int c0 = nt * 8 + 2 * kq;
            s[nt].x *= scale; s[nt].y *= scale;
            s[nt].z *= scale; s[nt].w *= scale;
            if (diag) {
                if (c0     > irow_lo + rowbias) s[nt].x = -INFINITY;
                if (c0 + 1 > irow_lo + rowbias) s[nt].y = -INFINITY;
                if (c0     > irow_hi + rowbias) s[nt].z = -INFINITY;
                if (c0 + 1 > irow_hi + rowbias) s[nt].w = -INFINITY;
            }
        }

        // ---- row max (local 16 + shuffle over 4-lane group)
        float rmax_lo = -INFINITY, rmax_hi = -INFINITY;
#pragma unroll
        for (int nt = 0; nt < 8; nt++) {
            rmax_lo = fmaxf(rmax_lo, fmaxf(s[nt].x, s[nt].y));
            rmax_hi = fmaxf(rmax_hi, fmaxf(s[nt].z, s[nt].w));
        }
        rmax_lo = fmaxf(rmax_lo, __shfl_xor_sync(0xffffffffu, rmax_lo, 1));
        rmax_lo = fmaxf(rmax_lo, __shfl_xor_sync(0xffffffffu, rmax_lo, 2));
        rmax_hi = fmaxf(rmax_hi, __shfl_xor_sync(0xffffffffu, rmax_hi, 1));
        rmax_hi = fmaxf(rmax_hi, __shfl_xor_sync(0xffffffffu, rmax_hi, 2));

        float mn_lo = fmaxf(m_lo, rmax_lo);
        float mn_hi = fmaxf(m_hi, rmax_hi);
        float alpha_lo = __expf(m_lo - mn_lo);
        float alpha_hi = __expf(m_hi - mn_hi);
        m_lo = mn_lo; m_hi = mn_hi;

        // ---- p = exp(s - m), write tf32(P) to smem, row sums (fp32 exact)
        float rsum_lo = 0.f, rsum_hi = 0.f;
#pragma unroll
        for (int nt = 0; nt < 8; nt++) {
            const int c0 = nt * 8 + 2 * kq;
            float px = __expf(s[nt].x - m_lo);
            float py = __expf(s[nt].y - m_lo);
            float pz = __expf(s[nt].z - m_hi);
            float pw = __expf(s[nt].w - m_hi);
            rsum_lo += px + py;
            rsum_hi += pz + pw;
            *(float2*)&Ps[irow_lo * AST + c0] = make_float2(tf32r(px), tf32r(py));
            *(float2*)&Ps[irow_hi * AST + c0] = make_float2(tf32r(pz), tf32r(pw));
        }
        rsum_lo += __shfl_xor_sync(0xffffffffu, rsum_lo, 1);
        rsum_lo += __shfl_xor_sync(0xffffffffu, rsum_lo, 2);
        rsum_hi += __shfl_xor_sync(0xffffffffu, rsum_hi, 1);
        rsum_hi += __shfl_xor_sync(0xffffffffu, rsum_hi, 2);

        l_lo = l_lo * alpha_lo + rsum_lo;
        l_hi = l_hi * alpha_hi + rsum_hi;
#pragma unroll
        for (int nt = 0; nt < 8; nt++) {
            o[nt].x *= alpha_lo; o[nt].y *= alpha_lo;
            o[nt].z *= alpha_hi; o[nt].w *= alpha_hi;
        }

        __syncthreads();   // all warps done reading K before V overwrite

        // ---- V load (tf32, natural layout): 4 float4 per thread
#pragma unroll
        for (int i = 0; i < 4; i++) {
            int idx = tid + i * 256;
            int row = idx >> 4;
            int c4  = (idx & 15) * 4;
            float4 v = *(const float4*)&Vg[row * HS + c4];
            float4 h4;
            h4.x = tf32r(v.x);
            h4.y = tf32r(v.y);
            h4.z = tf32r(v.z);
            h4.w = tf32r(v.w);
            *(float4*)&KVh[row * AST + c4] = h4;
        }
        __syncthreads();

        // ---- O += P V (both single-pass tf32: 1 mma)
#pragma unroll
        for (int ks = 0; ks < 8; ks++) {
            float ah[4];
            ah[0] = Ps[irow_lo * AST + 8 * ks + kq];
            ah[1] = Ps[irow_hi * AST + 8 * ks + kq];
            ah[2] = Ps[irow_lo * AST + 8 * ks + kq + 4];
            ah[3] = Ps[irow_hi * AST + 8 * ks + kq + 4];
#pragma unroll
            for (int nt = 0; nt < 8; nt++) {
                float bh[2];
                bh[0] = KVh[(8 * ks + kq) * AST + nt * 8 + r];
                bh[1] = KVh[(8 * ks + kq + 4) * AST + nt * 8 + r];
                mma_tf32(o[nt], ah, bh);
            }
        }
    }

    // ---- store partials (unnormalized) + m, l
    const size_t p = ((size_t)(bb * NQT2 + qt) * NCHUNK + cix);
#pragma unroll
    for (int nt = 0; nt < 8; nt++) {
        const int c0 = nt * 8 + 2 * (lane & 3);
        *(float2*)&g_po[p * (QROWS * 64) + irow_lo * 64 + c0] =
            make_float2(o[nt].x, o[nt].y);
        *(float2*)&g_po[p * (QROWS * 64) + irow_hi * 64 + c0] =
            make_float2(o[nt].z, o[nt].w);
    }
    if ((lane & 3) == 0) {
        g_pm[p * QROWS + irow_lo] = m_lo;
        g_pm[p * QROWS + irow_hi] = m_hi;
        g_pl[p * QROWS + irow_lo] = l_lo;
        g_pl[p * QROWS + irow_hi] = l_hi;
    }
}

// ---------------------------------------------------------------------------
// Kernel 3: combine split-KV partials.
// grid = (NQT2, BATCH, 8), block = 128; each CTA handles 16 rows.
// ---------------------------------------------------------------------------
__global__ __launch_bounds__(128) void attn_reduce(float* __restrict__ out)
{
    const int qt = blockIdx.x;             // 0..15 (128-row tiles)
    const int bb = blockIdx.y;
    const int rz = blockIdx.z;             // row group: rows rz*16..+15
    const int nc = qt / 2 + 1;             // chunks touching this q tile

    __shared__ float w[NCHUNK][16];
    __shared__ float invL[16];

    const int tid = threadIdx.x;
    const size_t pbase = (size_t)(bb * NQT2 + qt) * NCHUNK;

    if (tid < 16) {
        const int row = rz * 16 + tid;
        float M = -INFINITY;
        for (int c = 0; c < nc; c++)
            M = fmaxf(M, g_pm[(pbase + c) * QROWS + row]);
        float L = 0.f;
        for (int c = 0; c < nc; c++) {
            float wi = __expf(g_pm[(pbase + c) * QROWS + row] - M);
            w[c][tid] = wi;
            L += wi * g_pl[(pbase + c) * QROWS + row];
        }
        invL[tid] = 1.f / L;
    }
    __syncthreads();

#pragma unroll
    for (int i = 0; i < 2; i++) {
        int idx = tid + i * 128;           // 0..255 float4 slots
        int rl  = idx >> 4;                // 0..15
        int c4  = (idx & 15) * 4;
        const int row = rz * 16 + rl;
        float4 acc = make_float4(0.f, 0.f, 0.f, 0.f);
        for (int c = 0; c < nc; c++) {
            float4 v = *(const float4*)&g_po[(pbase + c) * (QROWS * 64) + row * 64 + c4];
            float wi = w[c][rl];
            acc.x = fmaf(wi, v.x, acc.x);
            acc.y = fmaf(wi, v.y, acc.y);
            acc.z = fmaf(wi, v.z, acc.z);
            acc.w = fmaf(wi, v.w, acc.w);
        }
        float inv = invL[rl];
        acc.x *= inv; acc.y *= inv; acc.z *= inv; acc.w *= inv;
        *(float4*)&out[((size_t)bb * SEQ + qt * QROWS + row) * HS + c4] = acc;
    }
}

// ---------------------------------------------------------------------------
extern "C" void kernel_launch(void* const* d_in, const int* in_sizes, int n_in,
                              void* d_out, int out_size)
{
    const float* xq  = (const float*)d_in[0];
    const float* xkv = (const float*)d_in[1];
    const float* Wq  = (const float*)d_in[2];
    const float* Wk  = (const float*)d_in[3];
    const float* Wv  = (const float*)d_in[4];
    float* out = (float*)d_out;

    const int attn_smem = (64 + QROWS) * AST * sizeof(float);   // 52224 B
    cudaFuncSetAttribute(attn_tc, cudaFuncAttributeMaxDynamicSharedMemorySize,
                         attn_smem);

    wsplit<<<192, 256>>>(Wq, Wk, Wv);
    qkv_tc<<<dim3(M_TOTAL / QBM, 3), 256>>>(xq, xkv);
    attn_tc<<<dim3(NQT2, NCHUNK, BATCH), 256, attn_smem>>>();
    attn_reduce<<<dim3(NQT2, BATCH, 8), 128>>>(out);
}

// round 15
// speedup vs baseline: 1.2499x; 1.2499x over previous
#include <cuda_runtime.h>
#include <math.h>
#include <stdint.h>

#define BATCH 8
#define SEQ   2048
#define CDIM  1024
#define HS    64
#define M_TOTAL (BATCH * SEQ)   // 16384

#define QROWS  128              // Q rows per attention CTA
#define NQT2   (SEQ / QROWS)    // 16 query tiles per batch
#define NCHUNK 8                // 8 KV chunks of 256 keys (4 tiles of 64)

// Scratch (device globals: allowed).
__device__ float g_q[M_TOTAL * HS];
__device__ float g_k[M_TOTAL * HS];
__device__ float g_v[M_TOTAL * HS];
__device__ float g_po[(size_t)BATCH * NQT2 * NCHUNK * QROWS * 64];
__device__ float g_pm[BATCH * NQT2 * NCHUNK * QROWS];
__device__ float g_pl[BATCH * NQT2 * NCHUNK * QROWS];
// Pre-truncated weights (tf32), layout [which][k][n]
__device__ float g_wh[3 * CDIM * HS];

// ---------------------------------------------------------------------------
// helpers
// ---------------------------------------------------------------------------
__device__ __forceinline__ float tf32r(float x) {
    uint32_t u;
    asm("cvt.rna.tf32.f32 %0, %1;" : "=r"(u) : "f"(x));
    return __uint_as_float(u);
}

__device__ __forceinline__ void mma_tf32(float4& d, const float* a, const float* b) {
    asm volatile(
        "mma.sync.aligned.m16n8k8.row.col.f32.tf32.tf32.f32 "
        "{%0,%1,%2,%3}, {%4,%5,%6,%7}, {%8,%9}, {%0,%1,%2,%3};"
        : "+f"(d.x), "+f"(d.y), "+f"(d.z), "+f"(d.w)
        : "r"(__float_as_uint(a[0])), "r"(__float_as_uint(a[1])),
          "r"(__float_as_uint(a[2])), "r"(__float_as_uint(a[3])),
          "r"(__float_as_uint(b[0])), "r"(__float_as_uint(b[1])));
}

__device__ __forceinline__ void cpa16(void* smem_dst, const void* gmem_src) {
    uint32_t s = (uint32_t)__cvta_generic_to_shared(smem_dst);
    asm volatile("cp.async.cg.shared.global [%0], [%1], 16;" :: "r"(s), "l"(gmem_src));
}
#define CP_COMMIT() asm volatile("cp.async.commit_group;")
#define CP_WAIT(n)  asm volatile("cp.async.wait_group %0;" :: "n"(n))

// ---------------------------------------------------------------------------
// Kernel 0: truncate W to tf32 (hi only). 49152 float4.
// ---------------------------------------------------------------------------
__global__ __launch_bounds__(256) void wsplit(
    const float* __restrict__ Wq, const float* __restrict__ Wk,
    const float* __restrict__ Wv)
{
    const int idx = blockIdx.x * 256 + threadIdx.x;      // float4 id, 0..49151
    const float* W = (idx < 16384) ? Wq : (idx < 32768 ? Wk : Wv);
    const int local = (idx & 16383) * 4;
    float4 w = *(const float4*)&W[local];
    float4 h;
    h.x = tf32r(w.x);
    h.y = tf32r(w.y);
    h.z = tf32r(w.z);
    h.w = tf32r(w.w);
    *(float4*)&g_wh[idx * 4] = h;
}

// ---------------------------------------------------------------------------
// Kernel 1: QKV projection, single-pass TF32 mma: acc += tf32(X)*tf32(W).
// 256 threads (8 warps), warp w owns rows w*16..+15 of the 128-row tile.
// ---------------------------------------------------------------------------
#define QBM 128
#define QBK 16
#define A_STR 20
#define B_STR 72
#define NKITER (CDIM / QBK)   // 64

__global__ __launch_bounds__(256) void qkv_tc(
    const float* __restrict__ xq, const float* __restrict__ xkv)
{
    const int which = blockIdx.y;                 // 0=Q, 1=K, 2=V
    const float* __restrict__ X  = (which == 0) ? xq : xkv;
    const float* __restrict__ WH = g_wh + which * CDIM * HS;
    float* __restrict__ O = (which == 0) ? g_q : (which == 1 ? g_k : g_v);

    __shared__ __align__(16) float As[2][QBM][A_STR];
    __shared__ __align__(16) float Bh[2][QBK][B_STR];

    const int tid  = threadIdx.x;
    const int warp = tid >> 5;
    const int lane = tid & 31;
    const int m0   = blockIdx.x * QBM;

    float4 acc[8];
#pragma unroll
    for (int nt = 0; nt < 8; nt++) acc[nt] = make_float4(0.f, 0.f, 0.f, 0.f);

    auto load_tile = [&](int it, int buf) {
        const int k0 = it * QBK;
#pragma unroll
        for (int i = 0; i < 2; i++) {
            int idx = tid + i * 256;       // 0..511
            int r   = idx >> 2;
            int c4  = (idx & 3) * 4;
            cpa16(&As[buf][r][c4], &X[(size_t)(m0 + r) * CDIM + k0 + c4]);
        }
        {
            int r  = tid >> 4;             // 0..15
            int c4 = (tid & 15) * 4;
            cpa16(&Bh[buf][r][c4], &WH[(size_t)(k0 + r) * HS + c4]);
        }
    };

    load_tile(0, 0);
    CP_COMMIT();

    const int arow = warp * 16 + (lane >> 2);
    const int kq   = lane & 3;
    const int bcol = lane >> 2;

    for (int it = 0; it < NKITER; it++) {
        const int buf = it & 1;
        if (it + 1 < NKITER) {
            load_tile(it + 1, buf ^ 1);
            CP_COMMIT();
            CP_WAIT(1);
        } else {
            CP_WAIT(0);
        }
        __syncthreads();

#pragma unroll
        for (int kk = 0; kk < 2; kk++) {
            const int ks = kk * 8;
            float ah[4];
            ah[0] = tf32r(As[buf][arow][ks + kq]);
            ah[1] = tf32r(As[buf][arow + 8][ks + kq]);
            ah[2] = tf32r(As[buf][arow][ks + kq + 4]);
            ah[3] = tf32r(As[buf][arow + 8][ks + kq + 4]);
#pragma unroll
            for (int nt = 0; nt < 8; nt++) {
                float bh[2];
                bh[0] = Bh[buf][ks + kq][nt * 8 + bcol];
                bh[1] = Bh[buf][ks + kq + 4][nt * 8 + bcol];
                mma_tf32(acc[nt], ah, bh);
            }
        }
        __syncthreads();
    }

    {
        const int row0 = m0 + warp * 16 + (lane >> 2);
#pragma unroll
        for (int nt = 0; nt < 8; nt++) {
            const int col = nt * 8 + 2 * (lane & 3);
            *(float2*)&O[(size_t)row0 * HS + col] =
                make_float2(acc[nt].x, acc[nt].y);
            *(float2*)&O[(size_t)(row0 + 8) * HS + col] =
                make_float2(acc[nt].z, acc[nt].w);
        }
    }
}

// ---------------------------------------------------------------------------
// Kernel 2: split-KV causal flash attention, 128-row Q tiles.
// grid = (NQT2, NCHUNK, BATCH), block = 256 (8 warps, 16 rows each).
// S and PV both single-pass tf32. K/V stored naturally.
// ---------------------------------------------------------------------------
#define AST 68

__global__ __launch_bounds__(256) void attn_tc(void)
{
    extern __shared__ float sm[];
    float* KVh = sm;                     // [64][AST]   (K, then V per kt)
    float* Ps  = sm + 64 * AST;          // [128][AST]

    const int qt  = blockIdx.x;          // 0..15 (128-row tiles)
    const int cix = blockIdx.y;          // 0..7
    const int bb  = blockIdx.z;
    if (2 * cix > qt) return;            // chunk entirely above diagonal

    const int tid  = threadIdx.x;
    const int warp = tid >> 5;           // 0..7
    const int lane = tid & 31;
    const int r    = lane >> 2;          // 0..7
    const int kq   = lane & 3;           // quad k
    const float scale = 0.03125f;        // 1024^-0.5

    const int irow_lo = warp * 16 + r;   // 0..127
    const int irow_hi = irow_lo + 8;

    // ---- Q fragments hoisted (single tf32)
    float qh[8][4];
    {
        const float* Qg = g_q + ((size_t)bb * SEQ + qt * QROWS + warp * 16) * HS;
#pragma unroll
        for (int ks = 0; ks < 8; ks++) {
            qh[ks][0] = tf32r(Qg[r * HS + 8 * ks + kq]);
            qh[ks][1] = tf32r(Qg[(r + 8) * HS + 8 * ks + kq]);
            qh[ks][2] = tf32r(Qg[r * HS + 8 * ks + kq + 4]);
            qh[ks][3] = tf32r(Qg[(r + 8) * HS + 8 * ks + kq + 4]);
        }
    }

    float4 o[8];
#pragma unroll
    for (int nt = 0; nt < 8; nt++) o[nt] = make_float4(0.f, 0.f, 0.f, 0.f);
    float m_lo = -INFINITY, m_hi = -INFINITY, l_lo = 0.f, l_hi = 0.f;

    const int kt_begin = cix * 4;
    const int kt_last  = 2 * qt + 1;     // last tile touching this Q block
    const int kt_end   = (cix * 4 + 3 < kt_last) ? (cix * 4 + 3) : kt_last;

    for (int kt = kt_begin; kt <= kt_end; kt++) {
        const float* Kg = g_k + ((size_t)bb * SEQ + kt * 64) * HS;
        const float* Vg = g_v + ((size_t)bb * SEQ + kt * 64) * HS;

        __syncthreads();   // prev-iter V reads (PV) done before K overwrite

        // ---- K load (tf32, natural layout): 4 float4 per thread
#pragma unroll
        for (int i = 0; i < 4; i++) {
            int idx = tid + i * 256;     // float4 id 0..1023
            int row = idx >> 4;
            int c4  = (idx & 15) * 4;
            float4 v = *(const float4*)&Kg[row * HS + c4];
            float4 h4;
            h4.x = tf32r(v.x);
            h4.y = tf32r(v.y);
            h4.z = tf32r(v.z);
            h4.w = tf32r(v.w);
            *(float4*)&KVh[row * AST + c4] = h4;
        }
        __syncthreads();

        // ---- S = Q K^T (single pass; B via 2 conflict-free scalar LDS)
        float4 s[8];
#pragma unroll
        for (int nt = 0; nt < 8; nt++) s[nt] = make_float4(0.f, 0.f, 0.f, 0.f);

#pragma unroll
        for (int ks = 0; ks < 8; ks++) {
#pragma unroll
            for (int nt = 0; nt < 8; nt++) {
                const int jrow = nt * 8 + r;
                float b[2];
                b[0] = KVh[jrow * AST + 8 * ks + kq];
                b[1] = KVh[jrow * AST + 8 * ks + kq + 4];
                mma_tf32(s[nt], qh[ks], b);
            }
        }

        // ---- scale + causal mask
        const int rowbias = qt * QROWS - kt * 64;
        const bool diag = (rowbias < 64);
#pragma unroll
        for (int nt = 0; nt < 8; nt++) {
            const int c0 = nt * 8 + 2 * kq;
            s[nt].x *= scale; s[nt].y *= scale;
            s[nt].z *= scale; s[nt].w *= scale;
            if (diag) {
                if (c0     > irow_lo + rowbias) s[nt].x = -INFINITY;
                if (c0 + 1 > irow_lo + rowbias) s[nt].y = -INFINITY;
                if (c0     > irow_hi + rowbias) s[nt].z = -INFINITY;
                if (c0 + 1 > irow_hi + rowbias) s[nt].w = -INFINITY;
            }
        }

        // ---- row max (local 16 + shuffle over 4-lane group)
        float rmax_lo = -INFINITY, rmax_hi = -INFINITY;
#pragma unroll
        for (int nt = 0; nt < 8; nt++) {
            rmax_lo = fmaxf(rmax_lo, fmaxf(s[nt].x, s[nt].y));
            rmax_hi = fmaxf(rmax_hi, fmaxf(s[nt].z, s[nt].w));
        }
        rmax_lo = fmaxf(rmax_lo, __shfl_xor_sync(0xffffffffu, rmax_lo, 1));
        rmax_lo = fmaxf(rmax_lo, __shfl_xor_sync(0xffffffffu, rmax_lo, 2));
        rmax_hi = fmaxf(rmax_hi, __shfl_xor_sync(0xffffffffu, rmax_hi, 1));
        rmax_hi = fmaxf(rmax_hi, __shfl_xor_sync(0xffffffffu, rmax_hi, 2));

        float mn_lo = fmaxf(m_lo, rmax_lo);
        float mn_hi = fmaxf(m_hi, rmax_hi);
        float alpha_lo = __expf(m_lo - mn_lo);
        float alpha_hi = __expf(m_hi - mn_hi);
        m_lo = mn_lo; m_hi = mn_hi;

        // ---- p = exp(s - m), write tf32(P) to smem, row sums (fp32 exact)
        float rsum_lo = 0.f, rsum_hi = 0.f;
#pragma unroll
        for (int nt = 0; nt < 8; nt++) {
            const int c0 = nt * 8 + 2 * kq;
            float px = __expf(s[nt].x - m_lo);
            float py = __expf(s[nt].y - m_lo);
            float pz = __expf(s[nt].z - m_hi);
            float pw = __expf(s[nt].w - m_hi);
            rsum_lo += px + py;
            rsum_hi += pz + pw;
            *(float2*)&Ps[irow_lo * AST + c0] = make_float2(tf32r(px), tf32r(py));
            *(float2*)&Ps[irow_hi * AST + c0] = make_float2(tf32r(pz), tf32r(pw));
        }
        rsum_lo += __shfl_xor_sync(0xffffffffu, rsum_lo, 1);
        rsum_lo += __shfl_xor_sync(0xffffffffu, rsum_lo, 2);
        rsum_hi += __shfl_xor_sync(0xffffffffu, rsum_hi, 1);
        rsum_hi += __shfl_xor_sync(0xffffffffu, rsum_hi, 2);

        l_lo = l_lo * alpha_lo + rsum_lo;
        l_hi = l_hi * alpha_hi + rsum_hi;
#pragma unroll
        for (int nt = 0; nt < 8; nt++) {
            o[nt].x *= alpha_lo; o[nt].y *= alpha_lo;
            o[nt].z *= alpha_hi; o[nt].w *= alpha_hi;
        }

        __syncthreads();   // all warps done reading K before V overwrite

        // ---- V load (tf32, natural layout): 4 float4 per thread
#pragma unroll
        for (int i = 0; i < 4; i++) {
            int idx = tid + i * 256;
            int row = idx >> 4;
            int c4  = (idx & 15) * 4;
            float4 v = *(const float4*)&Vg[row * HS + c4];
            float4 h4;
            h4.x = tf32r(v.x);
            h4.y = tf32r(v.y);
            h4.z = tf32r(v.z);
            h4.w = tf32r(v.w);
            *(float4*)&KVh[row * AST + c4] = h4;
        }
        __syncthreads();

        // ---- O += P V (both single-pass tf32: 1 mma)
#pragma unroll
        for (int ks = 0; ks < 8; ks++) {
            float ah[4];
            ah[0] = Ps[irow_lo * AST + 8 * ks + kq];
            ah[1] = Ps[irow_hi * AST + 8 * ks + kq];
            ah[2] = Ps[irow_lo * AST + 8 * ks + kq + 4];
            ah[3] = Ps[irow_hi * AST + 8 * ks + kq + 4];
#pragma unroll
            for (int nt = 0; nt < 8; nt++) {
                float bh[2];
                bh[0] = KVh[(8 * ks + kq) * AST + nt * 8 + r];
                bh[1] = KVh[(8 * ks + kq + 4) * AST + nt * 8 + r];
                mma_tf32(o[nt], ah, bh);
            }
        }
    }

    // ---- store partials (unnormalized) + m, l
    const size_t p = ((size_t)(bb * NQT2 + qt) * NCHUNK + cix);
#pragma unroll
    for (int nt = 0; nt < 8; nt++) {
        const int c0 = nt * 8 + 2 * (lane & 3);
        *(float2*)&g_po[p * (QROWS * 64) + irow_lo * 64 + c0] =
            make_float2(o[nt].x, o[nt].y);
        *(float2*)&g_po[p * (QROWS * 64) + irow_hi * 64 + c0] =
            make_float2(o[nt].z, o[nt].w);
    }
    if ((lane & 3) == 0) {
        g_pm[p * QROWS + irow_lo] = m_lo;
        g_pm[p * QROWS + irow_hi] = m_hi;
        g_pl[p * QROWS + irow_lo] = l_lo;
        g_pl[p * QROWS + irow_hi] = l_hi;
    }
}

// ---------------------------------------------------------------------------
// Kernel 3: combine split-KV partials.
// grid = (NQT2, BATCH, 8), block = 128; each CTA handles 16 rows.
// ---------------------------------------------------------------------------
__global__ __launch_bounds__(128) void attn_reduce(float* __restrict__ out)
{
    const int qt = blockIdx.x;             // 0..15 (128-row tiles)
    const int bb = blockIdx.y;
    const int rz = blockIdx.z;             // row group: rows rz*16..+15
    const int nc = qt / 2 + 1;             // chunks touching this q tile

    __shared__ float w[NCHUNK][16];
    __shared__ float invL[16];

    const int tid = threadIdx.x;
    const size_t pbase = (size_t)(bb * NQT2 + qt) * NCHUNK;

    if (tid < 16) {
        const int row = rz * 16 + tid;
        float M = -INFINITY;
        for (int c = 0; c < nc; c++)
            M = fmaxf(M, g_pm[(pbase + c) * QROWS + row]);
        float L = 0.f;
        for (int c = 0; c < nc; c++) {
            float wi = __expf(g_pm[(pbase + c) * QROWS + row] - M);
            w[c][tid] = wi;
            L += wi * g_pl[(pbase + c) * QROWS + row];
        }
        invL[tid] = 1.f / L;
    }
    __syncthreads();

#pragma unroll
    for (int i = 0; i < 2; i++) {
        int idx = tid + i * 128;           // 0..255 float4 slots
        int rl  = idx >> 4;                // 0..15
        int c4  = (idx & 15) * 4;
        const int row = rz * 16 + rl;
        float4 acc = make_float4(0.f, 0.f, 0.f, 0.f);
        for (int c = 0; c < nc; c++) {
            float4 v = *(const float4*)&g_po[(pbase + c) * (QROWS * 64) + row * 64 + c4];
            float wi = w[c][rl];
            acc.x = fmaf(wi, v.x, acc.x);
            acc.y = fmaf(wi, v.y, acc.y);
            acc.z = fmaf(wi, v.z, acc.z);
            acc.w = fmaf(wi, v.w, acc.w);
        }
        float inv = invL[rl];
        acc.x *= inv; acc.y *= inv; acc.z *= inv; acc.w *= inv;
        *(float4*)&out[((size_t)bb * SEQ + qt * QROWS + row) * HS + c4] = acc;
    }
}

// ---------------------------------------------------------------------------
extern "C" void kernel_launch(void* const* d_in, const int* in_sizes, int n_in,
                              void* d_out, int out_size)
{
    const float* xq  = (const float*)d_in[0];
    const float* xkv = (const float*)d_in[1];
    const float* Wq  = (const float*)d_in[2];
    const float* Wk  = (const float*)d_in[3];
    const float* Wv  = (const float*)d_in[4];
    float* out = (float*)d_out;

    const int attn_smem = (64 + QROWS) * AST * sizeof(float);   // 52224 B
    cudaFuncSetAttribute(attn_tc, cudaFuncAttributeMaxDynamicSharedMemorySize,
                         attn_smem);

    wsplit<<<192, 256>>>(Wq, Wk, Wv);
    qkv_tc<<<dim3(M_TOTAL / QBM, 3), 256>>>(xq, xkv);
    attn_tc<<<dim3(NQT2, NCHUNK, BATCH), 256, attn_smem>>>();
    attn_reduce<<<dim3(NQT2, BATCH, 8), 128>>>(out);
}

// round 16
// speedup vs baseline: 1.3527x; 1.0822x over previous
#include <cuda_runtime.h>
#include <math.h>
#include <stdint.h>

#define BATCH 8
#define SEQ   2048
#define CDIM  1024
#define HS    64
#define M_TOTAL (BATCH * SEQ)   // 16384

#define QROWS  128              // Q rows per attention CTA
#define NQT2   (SEQ / QROWS)    // 16 query tiles per batch
#define NCHUNK 8                // 8 KV chunks of 256 keys (4 tiles of 64)

// Scratch (device globals: allowed).
__device__ float g_q[M_TOTAL * HS];
__device__ float g_k[M_TOTAL * HS];
__device__ float g_v[M_TOTAL * HS];
__device__ float g_po[(size_t)BATCH * NQT2 * NCHUNK * QROWS * 64];
__device__ float g_pm[BATCH * NQT2 * NCHUNK * QROWS];
__device__ float g_pl[BATCH * NQT2 * NCHUNK * QROWS];
// Pre-truncated weights (tf32), layout [which][k][n]
__device__ float g_wh[3 * CDIM * HS];

// ---------------------------------------------------------------------------
// helpers
// ---------------------------------------------------------------------------
__device__ __forceinline__ float tf32r(float x) {
    uint32_t u;
    asm("cvt.rna.tf32.f32 %0, %1;" : "=r"(u) : "f"(x));
    return __uint_as_float(u);
}

__device__ __forceinline__ void mma_tf32(float4& d, const float* a, const float* b) {
    asm volatile(
        "mma.sync.aligned.m16n8k8.row.col.f32.tf32.tf32.f32 "
        "{%0,%1,%2,%3}, {%4,%5,%6,%7}, {%8,%9}, {%0,%1,%2,%3};"
        : "+f"(d.x), "+f"(d.y), "+f"(d.z), "+f"(d.w)
        : "r"(__float_as_uint(a[0])), "r"(__float_as_uint(a[1])),
          "r"(__float_as_uint(a[2])), "r"(__float_as_uint(a[3])),
          "r"(__float_as_uint(b[0])), "r"(__float_as_uint(b[1])));
}

__device__ __forceinline__ void cpa16(void* smem_dst, const void* gmem_src) {
    uint32_t s = (uint32_t)__cvta_generic_to_shared(smem_dst);
    asm volatile("cp.async.cg.shared.global [%0], [%1], 16;" :: "r"(s), "l"(gmem_src));
}
#define CP_COMMIT() asm volatile("cp.async.commit_group;")
#define CP_WAIT(n)  asm volatile("cp.async.wait_group %0;" :: "n"(n))

// ---------------------------------------------------------------------------
// Kernel 0: truncate W to tf32 (hi only). 49152 float4.
// ---------------------------------------------------------------------------
__global__ __launch_bounds__(256) void wsplit(
    const float* __restrict__ Wq, const float* __restrict__ Wk,
    const float* __restrict__ Wv)
{
    const int idx = blockIdx.x * 256 + threadIdx.x;      // float4 id, 0..49151
    const float* W = (idx < 16384) ? Wq : (idx < 32768 ? Wk : Wv);
    const int local = (idx & 16383) * 4;
    float4 w = *(const float4*)&W[local];
    float4 h;
    h.x = tf32r(w.x);
    h.y = tf32r(w.y);
    h.z = tf32r(w.z);
    h.w = tf32r(w.w);
    *(float4*)&g_wh[idx * 4] = h;
}

// ---------------------------------------------------------------------------
// Kernel 1: QKV projection, single-pass TF32 mma: acc += tf32(X)*tf32(W).
// 256 threads (8 warps), warp w owns rows w*16..+15 of the 128-row tile.
// ---------------------------------------------------------------------------
#define QBM 128
#define QBK 16
#define A_STR 20
#define B_STR 72
#define NKITER (CDIM / QBK)   // 64

__global__ __launch_bounds__(256) void qkv_tc(
    const float* __restrict__ xq, const float* __restrict__ xkv)
{
    const int which = blockIdx.y;                 // 0=Q, 1=K, 2=V
    const float* __restrict__ X  = (which == 0) ? xq : xkv;
    const float* __restrict__ WH = g_wh + which * CDIM * HS;
    float* __restrict__ O = (which == 0) ? g_q : (which == 1 ? g_k : g_v);

    __shared__ __align__(16) float As[2][QBM][A_STR];
    __shared__ __align__(16) float Bh[2][QBK][B_STR];

    const int tid  = threadIdx.x;
    const int warp = tid >> 5;
    const int lane = tid & 31;
    const int m0   = blockIdx.x * QBM;

    float4 acc[8];
#pragma unroll
    for (int nt = 0; nt < 8; nt++) acc[nt] = make_float4(0.f, 0.f, 0.f, 0.f);

    auto load_tile = [&](int it, int buf) {
        const int k0 = it * QBK;
#pragma unroll
        for (int i = 0; i < 2; i++) {
            int idx = tid + i * 256;       // 0..511
            int r   = idx >> 2;
            int c4  = (idx & 3) * 4;
            cpa16(&As[buf][r][c4], &X[(size_t)(m0 + r) * CDIM + k0 + c4]);
        }
        {
            int r  = tid >> 4;             // 0..15
            int c4 = (tid & 15) * 4;
            cpa16(&Bh[buf][r][c4], &WH[(size_t)(k0 + r) * HS + c4]);
        }
    };

    load_tile(0, 0);
    CP_COMMIT();

    const int arow = warp * 16 + (lane >> 2);
    const int kq   = lane & 3;
    const int bcol = lane >> 2;

    for (int it = 0; it < NKITER; it++) {
        const int buf = it & 1;
        if (it + 1 < NKITER) {
            load_tile(it + 1, buf ^ 1);
            CP_COMMIT();
            CP_WAIT(1);
        } else {
            CP_WAIT(0);
        }
        __syncthreads();

#pragma unroll
        for (int kk = 0; kk < 2; kk++) {
            const int ks = kk * 8;
            float ah[4];
            ah[0] = tf32r(As[buf][arow][ks + kq]);
            ah[1] = tf32r(As[buf][arow + 8][ks + kq]);
            ah[2] = tf32r(As[buf][arow][ks + kq + 4]);
            ah[3] = tf32r(As[buf][arow + 8][ks + kq + 4]);
#pragma unroll
            for (int nt = 0; nt < 8; nt++) {
                float bh[2];
                bh[0] = Bh[buf][ks + kq][nt * 8 + bcol];
                bh[1] = Bh[buf][ks + kq + 4][nt * 8 + bcol];
                mma_tf32(acc[nt], ah, bh);
            }
        }
        __syncthreads();
    }

    {
        const int row0 = m0 + warp * 16 + (lane >> 2);
#pragma unroll
        for (int nt = 0; nt < 8; nt++) {
            const int col = nt * 8 + 2 * (lane & 3);
            *(float2*)&O[(size_t)row0 * HS + col] =
                make_float2(acc[nt].x, acc[nt].y);
            *(float2*)&O[(size_t)(row0 + 8) * HS + col] =
                make_float2(acc[nt].z, acc[nt].w);
        }
    }
}

// ---------------------------------------------------------------------------
// Kernel 2: split-KV causal flash attention, 128-row Q tiles, PIPELINED.
// grid = (NQT2, NCHUNK, BATCH), block = 256 (8 warps, 16 rows each).
// K+V for tile kt+1 staged via cp.async (double-buffered raw fp32) while
// tile kt computes; in-place cvt pass to tf32 after the wait.
// smem: K[2][64][AST] + V[2][64][AST] + Ps[128][AST] = 102 KB.
// ---------------------------------------------------------------------------
#define AST 68
#define KVF (64 * AST)          // floats per K (or V) tile buffer

__global__ __launch_bounds__(256) void attn_tc(void)
{
    extern __shared__ float sm[];
    // layout: Kbuf0, Vbuf0, Kbuf1, Vbuf1, Ps
    float* Ps = sm + 4 * KVF;            // [128][AST]

    const int qt  = blockIdx.x;          // 0..15 (128-row tiles)
    const int cix = blockIdx.y;          // 0..7
    const int bb  = blockIdx.z;
    if (2 * cix > qt) return;            // chunk entirely above diagonal

    const int tid  = threadIdx.x;
    const int warp = tid >> 5;           // 0..7
    const int lane = tid & 31;
    const int r    = lane >> 2;          // 0..7
    const int kq   = lane & 3;           // quad k
    const float scale = 0.03125f;        // 1024^-0.5

    const int irow_lo = warp * 16 + r;   // 0..127
    const int irow_hi = irow_lo + 8;

    // ---- Q fragments hoisted (single tf32)
    float qh[8][4];
    {
        const float* Qg = g_q + ((size_t)bb * SEQ + qt * QROWS + warp * 16) * HS;
#pragma unroll
        for (int ks = 0; ks < 8; ks++) {
            qh[ks][0] = tf32r(Qg[r * HS + 8 * ks + kq]);
            qh[ks][1] = tf32r(Qg[(r + 8) * HS + 8 * ks + kq]);
            qh[ks][2] = tf32r(Qg[r * HS + 8 * ks + kq + 4]);
            qh[ks][3] = tf32r(Qg[(r + 8) * HS + 8 * ks + kq + 4]);
        }
    }

    float4 o[8];
#pragma unroll
    for (int nt = 0; nt < 8; nt++) o[nt] = make_float4(0.f, 0.f, 0.f, 0.f);
    float m_lo = -INFINITY, m_hi = -INFINITY, l_lo = 0.f, l_hi = 0.f;

    const int kt_begin = cix * 4;
    const int kt_last  = 2 * qt + 1;     // last tile touching this Q block
    const int kt_end   = (cix * 4 + 3 < kt_last) ? (cix * 4 + 3) : kt_last;

    // issue K+V tile loads for kt into buffer b (raw fp32, 8 cpa16/thread)
    auto issue_kv = [&](int kt, int b) {
        const float* Kg = g_k + ((size_t)bb * SEQ + kt * 64) * HS;
        const float* Vg = g_v + ((size_t)bb * SEQ + kt * 64) * HS;
        float* Kb = sm + (2 * b) * KVF;
        float* Vb = sm + (2 * b + 1) * KVF;
#pragma unroll
        for (int i = 0; i < 4; i++) {
            int idx = tid + i * 256;     // float4 id 0..1023
            int row = idx >> 4;
            int c4  = (idx & 15) * 4;
            cpa16(&Kb[row * AST + c4], &Kg[row * HS + c4]);
            cpa16(&Vb[row * AST + c4], &Vg[row * HS + c4]);
        }
    };

    issue_kv(kt_begin, 0);
    CP_COMMIT();

    for (int kt = kt_begin; kt <= kt_end; kt++) {
        const int buf = (kt - kt_begin) & 1;
        float* Kc = sm + (2 * buf) * KVF;
        float* Vc = sm + (2 * buf + 1) * KVF;

        CP_WAIT(0);
        __syncthreads();   // buf filled; all warps done reading buf^1 (prev iter)

        if (kt + 1 <= kt_end) {
            issue_kv(kt + 1, buf ^ 1);
            CP_COMMIT();
        }

        // ---- in-place cvt pass: raw fp32 -> tf32 (K and V of buf)
#pragma unroll
        for (int i = 0; i < 4; i++) {
            int idx = tid + i * 256;
            int row = idx >> 4;
            int c4  = (idx & 15) * 4;
            float4 kv = *(float4*)&Kc[row * AST + c4];
            kv.x = tf32r(kv.x); kv.y = tf32r(kv.y);
            kv.z = tf32r(kv.z); kv.w = tf32r(kv.w);
            *(float4*)&Kc[row * AST + c4] = kv;
            float4 vv = *(float4*)&Vc[row * AST + c4];
            vv.x = tf32r(vv.x); vv.y = tf32r(vv.y);
            vv.z = tf32r(vv.z); vv.w = tf32r(vv.w);
            *(float4*)&Vc[row * AST + c4] = vv;
        }
        __syncthreads();   // cvt'd tiles visible to all warps

        // ---- S = Q K^T (single pass; B via 2 conflict-free scalar LDS)
        float4 s[8];
#pragma unroll
        for (int nt = 0; nt < 8; nt++) s[nt] = make_float4(0.f, 0.f, 0.f, 0.f);

#pragma unroll
        for (int ks = 0; ks < 8; ks++) {
#pragma unroll
            for (int nt = 0; nt < 8; nt++) {
                const int jrow = nt * 8 + r;
                float b[2];
                b[0] = Kc[jrow * AST + 8 * ks + kq];
                b[1] = Kc[jrow * AST + 8 * ks + kq + 4];
                mma_tf32(s[nt], qh[ks], b);
            }
        }

        // ---- scale + causal mask
        const int rowbias = qt * QROWS - kt * 64;
        const bool diag = (rowbias < 64);
#pragma unroll
        for (int nt = 0; nt < 8; nt++) {
            const int c0 = nt * 8 + 2 * kq;
            s[nt].x *= scale; s[nt].y *= scale;
            s[nt].z *= scale; s[nt].w *= scale;
            if (diag) {
                if (c0     > irow_lo + rowbias) s[nt].x = -INFINITY;
                if (c0 + 1 > irow_lo + rowbias) s[nt].y = -INFINITY;
                if (c0     > irow_hi + rowbias) s[nt].z = -INFINITY;
                if (c0 + 1 > irow_hi + rowbias) s[nt].w = -INFINITY;
            }
        }

        // ---- row max (local 16 + shuffle over 4-lane group)
        float rmax_lo = -INFINITY, rmax_hi = -INFINITY;
#pragma unroll
        for (int nt = 0; nt < 8; nt++) {
            rmax_lo = fmaxf(rmax_lo, fmaxf(s[nt].x, s[nt].y));
            rmax_hi = fmaxf(rmax_hi, fmaxf(s[nt].z, s[nt].w));
        }
        rmax_lo = fmaxf(rmax_lo, __shfl_xor_sync(0xffffffffu, rmax_lo, 1));
        rmax_lo = fmaxf(rmax_lo, __shfl_xor_sync(0xffffffffu, rmax_lo, 2));
        rmax_hi = fmaxf(rmax_hi, __shfl_xor_sync(0xffffffffu, rmax_hi, 1));
        rmax_hi = fmaxf(rmax_hi, __shfl_xor_sync(0xffffffffu, rmax_hi, 2));

        float mn_lo = fmaxf(m_lo, rmax_lo);
        float mn_hi = fmaxf(m_hi, rmax_hi);
        float alpha_lo = __expf(m_lo - mn_lo);
        float alpha_hi = __expf(m_hi - mn_hi);
        m_lo = mn_lo; m_hi = mn_hi;

        // ---- p = exp(s - m), write tf32(P) to smem (own rows), row sums
        float rsum_lo = 0.f, rsum_hi = 0.f;
#pragma unroll
        for (int nt = 0; nt < 8; nt++) {
            const int c0 = nt * 8 + 2 * kq;
            float px = __expf(s[nt].x - m_lo);
            float py = __expf(s[nt].y - m_lo);
            float pz = __expf(s[nt].z - m_hi);
            float pw = __expf(s[nt].w - m_hi);
            rsum_lo += px + py;
            rsum_hi += pz + pw;
            *(float2*)&Ps[irow_lo * AST + c0] = make_float2(tf32r(px), tf32r(py));
            *(float2*)&Ps[irow_hi * AST + c0] = make_float2(tf32r(pz), tf32r(pw));
        }
        rsum_lo += __shfl_xor_sync(0xffffffffu, rsum_lo, 1);
        rsum_lo += __shfl_xor_sync(0xffffffffu, rsum_lo, 2);
        rsum_hi += __shfl_xor_sync(0xffffffffu, rsum_hi, 1);
        rsum_hi += __shfl_xor_sync(0xffffffffu, rsum_hi, 2);

        l_lo = l_lo * alpha_lo + rsum_lo;
        l_hi = l_hi * alpha_hi + rsum_hi;
#pragma unroll
        for (int nt = 0; nt < 8; nt++) {
            o[nt].x *= alpha_lo; o[nt].y *= alpha_lo;
            o[nt].z *= alpha_hi; o[nt].w *= alpha_hi;
        }

        // ---- O += P V (P rows are warp-private: no sync needed)
#pragma unroll
        for (int ks = 0; ks < 8; ks++) {
            float ah[4];
            ah[0] = Ps[irow_lo * AST + 8 * ks + kq];
            ah[1] = Ps[irow_hi * AST + 8 * ks + kq];
            ah[2] = Ps[irow_lo * AST + 8 * ks + kq + 4];
            ah[3] = Ps[irow_hi * AST + 8 * ks + kq + 4];
#pragma unroll
            for (int nt = 0; nt < 8; nt++) {
                float bh[2];
                bh[0] = Vc[(8 * ks + kq) * AST + nt * 8 + r];
                bh[1] = Vc[(8 * ks + kq + 4) * AST + nt * 8 + r];
                mma_tf32(o[nt], ah, bh);
            }
        }
    }

    // ---- store partials (unnormalized) + m, l
    const size_t p = ((size_t)(bb * NQT2 + qt) * NCHUNK + cix);
#pragma unroll
    for (int nt = 0; nt < 8; nt++) {
        const int c0 = nt * 8 + 2 * (lane & 3);
        *(float2*)&g_po[p * (QROWS * 64) + irow_lo * 64 + c0] =
            make_float2(o[nt].x, o[nt].y);
        *(float2*)&g_po[p * (QROWS * 64) + irow_hi * 64 + c0] =
            make_float2(o[nt].z, o[nt].w);
    }
    if ((lane & 3) == 0) {
        g_pm[p * QROWS + irow_lo] = m_lo;
        g_pm[p * QROWS + irow_hi] = m_hi;
        g_pl[p * QROWS + irow_lo] = l_lo;
        g_pl[p * QROWS + irow_hi] = l_hi;
    }
}

// ---------------------------------------------------------------------------
// Kernel 3: combine split-KV partials.
// grid = (NQT2, BATCH, 8), block = 128; each CTA handles 16 rows.
// ---------------------------------------------------------------------------
__global__ __launch_bounds__(128) void attn_reduce(float* __restrict__ out)
{
    const int qt = blockIdx.x;             // 0..15 (128-row tiles)
    const int bb = blockIdx.y;
    const int rz = blockIdx.z;             // row group: rows rz*16..+15
    const int nc = qt / 2 + 1;             // chunks touching this q tile

    __shared__ float w[NCHUNK][16];
    __shared__ float invL[16];

    const int tid = threadIdx.x;
    const size_t pbase = (size_t)(bb * NQT2 + qt) * NCHUNK;

    if (tid < 16) {
        const int row = rz * 16 + tid;
        float M = -INFINITY;
        for (int c = 0; c < nc; c++)
            M = fmaxf(M, g_pm[(pbase + c) * QROWS + row]);
        float L = 0.f;
        for (int c = 0; c < nc; c++) {
            float wi = __expf(g_pm[(pbase + c) * QROWS + row] - M);
            w[c][tid] = wi;
            L += wi * g_pl[(pbase + c) * QROWS + row];
        }
        invL[tid] = 1.f / L;
    }
    __syncthreads();

#pragma unroll
    for (int i = 0; i < 2; i++) {
        int idx = tid + i * 128;           // 0..255 float4 slots
        int rl  = idx >> 4;                // 0..15
        int c4  = (idx & 15) * 4;
        const int row = rz * 16 + rl;
        float4 acc = make_float4(0.f, 0.f, 0.f, 0.f);
        for (int c = 0; c < nc; c++) {
            float4 v = *(const float4*)&g_po[(pbase + c) * (QROWS * 64) + row * 64 + c4];
            float wi = w[c][rl];
            acc.x = fmaf(wi, v.x, acc.x);
            acc.y = fmaf(wi, v.y, acc.y);
            acc.z = fmaf(wi, v.z, acc.z);
            acc.w = fmaf(wi, v.w, acc.w);
        }
        float inv = invL[rl];
        acc.x *= inv; acc.y *= inv; acc.z *= inv; acc.w *= inv;
        *(float4*)&out[((size_t)bb * SEQ + qt * QROWS + row) * HS + c4] = acc;
    }
}

// ---------------------------------------------------------------------------
extern "C" void kernel_launch(void* const* d_in, const int* in_sizes, int n_in,
                              void* d_out, int out_size)
{
    const float* xq  = (const float*)d_in[0];
    const float* xkv = (const float*)d_in[1];
    const float* Wq  = (const float*)d_in[2];
    const float* Wk  = (const float*)d_in[3];
    const float* Wv  = (const float*)d_in[4];
    float* out = (float*)d_out;

    const int attn_smem = (4 * KVF + QROWS * AST) * sizeof(float);   // 104448 B
    cudaFuncSetAttribute(attn_tc, cudaFuncAttributeMaxDynamicSharedMemorySize,
                         attn_smem);

    wsplit<<<192, 256>>>(Wq, Wk, Wv);
    qkv_tc<<<dim3(M_TOTAL / QBM, 3), 256>>>(xq, xkv);
    attn_tc<<<dim3(NQT2, NCHUNK, BATCH), 256, attn_smem>>>();
    attn_reduce<<<dim3(NQT2, BATCH, 8), 128>>>(out);
}